// round 7
// baseline (speedup 1.0000x reference)
#include <cuda_runtime.h>

#define B_ 8
#define C_ 64
#define H_ 256
#define W_ 256
#define HW_ (H_ * W_)

// 2 px per thread (float2). No shared memory, no barriers: rely on L2 halo
// dedup (proven minimal DRAM in R1) + high occupancy for latency hiding.
// Warp = 64 contiguous px of one row -> h warp-uniform.
__global__ __launch_bounds__(256, 6)
void conv_attn_f2(const float* __restrict__ q,
                  const float* __restrict__ k,
                  const float* __restrict__ v,
                  float* __restrict__ out)
{
    const int t  = threadIdx.x & 127;        // 128 px-pairs per row
    const int w0 = t * 2;                    // 0..254
    const int h  = blockIdx.y * 2 + (threadIdx.x >> 7);
    const int b  = blockIdx.z;

    const size_t cb = (size_t)b * C_ * HW_;
    const int rowoff = h * W_ + w0;

    const bool has_left  = (w0 > 0);
    const bool has_right = (w0 + 2 < W_);

    float s[2][9];
#pragma unroll
    for (int j = 0; j < 2; j++)
#pragma unroll
        for (int i = 0; i < 9; i++) s[j][i] = 0.0f;

    // ---------------- Pass 1: scores ----------------
#pragma unroll 2
    for (int c = 0; c < C_; c++) {
        const float* qc = q + cb + (size_t)c * HW_;
        const float* kc = k + cb + (size_t)c * HW_;

        const float2 qv = *reinterpret_cast<const float2*>(qc + rowoff);

#pragma unroll
        for (int dy = 0; dy < 3; dy++) {
            const int hh = h + dy - 1;
            if (hh < 0 || hh >= H_) continue;          // warp-uniform
            const float* row = kc + hh * W_ + w0;

            const float2 m = *reinterpret_cast<const float2*>(row);
            const float  l = has_left  ? __ldg(row - 1) : 0.0f;
            const float  r = has_right ? __ldg(row + 2) : 0.0f;

            // px0 taps: l, m.x, m.y   px1 taps: m.x, m.y, r
            s[0][dy*3+0] = fmaf(qv.x, l,   s[0][dy*3+0]);
            s[0][dy*3+1] = fmaf(qv.x, m.x, s[0][dy*3+1]);
            s[0][dy*3+2] = fmaf(qv.x, m.y, s[0][dy*3+2]);
            s[1][dy*3+0] = fmaf(qv.y, m.x, s[1][dy*3+0]);
            s[1][dy*3+1] = fmaf(qv.y, m.y, s[1][dy*3+1]);
            s[1][dy*3+2] = fmaf(qv.y, r,   s[1][dy*3+2]);
        }
    }

    // ---------------- Softmax over 9 taps (OOB taps carry score 0 = zero-pad) ----------------
#pragma unroll
    for (int j = 0; j < 2; j++) {
        float mx = s[j][0];
#pragma unroll
        for (int i = 1; i < 9; i++) mx = fmaxf(mx, s[j][i]);
        float sum = 0.0f;
#pragma unroll
        for (int i = 0; i < 9; i++) { s[j][i] = __expf(s[j][i] - mx); sum += s[j][i]; }
        const float inv = 1.0f / sum;
#pragma unroll
        for (int i = 0; i < 9; i++) s[j][i] *= inv;
    }

    // ---------------- Pass 2: weighted v sum ----------------
#pragma unroll 2
    for (int c = 0; c < C_; c++) {
        const float* vc = v + cb + (size_t)c * HW_;

        float acc0 = 0.0f, acc1 = 0.0f;

#pragma unroll
        for (int dy = 0; dy < 3; dy++) {
            const int hh = h + dy - 1;
            if (hh < 0 || hh >= H_) continue;
            const float* row = vc + hh * W_ + w0;

            const float2 m = *reinterpret_cast<const float2*>(row);
            const float  l = has_left  ? __ldg(row - 1) : 0.0f;
            const float  r = has_right ? __ldg(row + 2) : 0.0f;

            acc0 = fmaf(s[0][dy*3+0], l,   acc0);
            acc0 = fmaf(s[0][dy*3+1], m.x, acc0);
            acc0 = fmaf(s[0][dy*3+2], m.y, acc0);
            acc1 = fmaf(s[1][dy*3+0], m.x, acc1);
            acc1 = fmaf(s[1][dy*3+1], m.y, acc1);
            acc1 = fmaf(s[1][dy*3+2], r,   acc1);
        }

        float2 o; o.x = acc0; o.y = acc1;
        *reinterpret_cast<float2*>(out + cb + (size_t)c * HW_ + rowoff) = o;
    }
}

extern "C" void kernel_launch(void* const* d_in, const int* in_sizes, int n_in,
                              void* d_out, int out_size)
{
    const float* q = (const float*)d_in[0];
    const float* k = (const float*)d_in[1];
    const float* v = (const float*)d_in[2];
    float* out = (float*)d_out;

    dim3 block(256);            // 2 rows x 128 px-pairs
    dim3 grid(1, H_ / 2, B_);   // 1024 blocks
    conv_attn_f2<<<grid, block>>>(q, k, v, out);
}

// round 8
// speedup vs baseline: 1.5034x; 1.5034x over previous
#include <cuda_runtime.h>

#define B_ 8
#define C_ 64
#define H_ 256
#define W_ 256
#define HW_ (H_ * W_)

// 2 px (w) x 2 rows (h) per thread. Register vertical reuse: 4 window rows
// serve 2 output rows (1.33 loads per output-row instead of 3).
// No smem, no barriers. blockDim (128,2): warp = 64 contiguous px of one
// row-pair -> row predicates warp-uniform.
__global__ __launch_bounds__(256, 3)
void conv_attn_rr(const float* __restrict__ q,
                  const float* __restrict__ k,
                  const float* __restrict__ v,
                  float* __restrict__ out)
{
    const int tx = threadIdx.x;                    // 0..127
    const int w0 = tx * 2;                         // 0..254
    const int h0 = blockIdx.y * 4 + threadIdx.y * 2;   // first of 2 output rows
    const int b  = blockIdx.z;

    const size_t cb = (size_t)b * C_ * HW_;
    const float* qb = q + cb;
    const float* kb = k + cb;
    const float* vb = v + cb;
    float*       ob = out + cb;

    const bool hl = (w0 > 0);
    const bool hr = (w0 + 2 < W_);

    // window rows h0-1 .. h0+2
    int  ro[4];
    bool rv[4];
#pragma unroll
    for (int wr = 0; wr < 4; wr++) {
        ro[wr] = h0 - 1 + wr;
        rv[wr] = (ro[wr] >= 0) && (ro[wr] < H_);
    }

    // scores: [out-row][px][tap]
    float s[2][2][9];
#pragma unroll
    for (int r = 0; r < 2; r++)
#pragma unroll
        for (int j = 0; j < 2; j++)
#pragma unroll
            for (int i = 0; i < 9; i++) s[r][j][i] = 0.0f;

    // ================= Pass 1: scores =================
#pragma unroll 1
    for (int c = 0; c < C_; c++) {
        const float* qc = qb + (size_t)c * HW_;
        const float* kc = kb + (size_t)c * HW_;

        const float2 qa = *reinterpret_cast<const float2*>(qc + h0 * W_ + w0);
        const float2 qd = *reinterpret_cast<const float2*>(qc + (h0 + 1) * W_ + w0);

        float a[4][4];
#pragma unroll
        for (int wr = 0; wr < 4; wr++) {
            if (rv[wr]) {
                const float* row = kc + ro[wr] * W_ + w0;
                const float2 m = *reinterpret_cast<const float2*>(row);
                a[wr][0] = hl ? __ldg(row - 1) : 0.0f;
                a[wr][1] = m.x;
                a[wr][2] = m.y;
                a[wr][3] = hr ? __ldg(row + 2) : 0.0f;
            } else {
                a[wr][0] = a[wr][1] = a[wr][2] = a[wr][3] = 0.0f;
            }
        }

#pragma unroll
        for (int wr = 0; wr < 4; wr++) {
            if (wr < 3) {          // output row 0, dy = wr
#pragma unroll
                for (int dx = 0; dx < 3; dx++) {
                    s[0][0][wr * 3 + dx] = fmaf(qa.x, a[wr][dx],     s[0][0][wr * 3 + dx]);
                    s[0][1][wr * 3 + dx] = fmaf(qa.y, a[wr][dx + 1], s[0][1][wr * 3 + dx]);
                }
            }
            if (wr > 0) {          // output row 1, dy = wr-1
                const int dy = wr - 1;
#pragma unroll
                for (int dx = 0; dx < 3; dx++) {
                    s[1][0][dy * 3 + dx] = fmaf(qd.x, a[wr][dx],     s[1][0][dy * 3 + dx]);
                    s[1][1][dy * 3 + dx] = fmaf(qd.y, a[wr][dx + 1], s[1][1][dy * 3 + dx]);
                }
            }
        }
    }

    // ================= Softmax over 9 taps (OOB taps carry score 0 = zero-pad) =================
#pragma unroll
    for (int r = 0; r < 2; r++)
#pragma unroll
        for (int j = 0; j < 2; j++) {
            float mx = s[r][j][0];
#pragma unroll
            for (int i = 1; i < 9; i++) mx = fmaxf(mx, s[r][j][i]);
            float sum = 0.0f;
#pragma unroll
            for (int i = 0; i < 9; i++) { s[r][j][i] = __expf(s[r][j][i] - mx); sum += s[r][j][i]; }
            const float inv = 1.0f / sum;
#pragma unroll
            for (int i = 0; i < 9; i++) s[r][j][i] *= inv;
        }

    // ================= Pass 2: weighted v sum =================
#pragma unroll 1
    for (int c = 0; c < C_; c++) {
        const float* vc = vb + (size_t)c * HW_;

        float a[4][4];
#pragma unroll
        for (int wr = 0; wr < 4; wr++) {
            if (rv[wr]) {
                const float* row = vc + ro[wr] * W_ + w0;
                const float2 m = *reinterpret_cast<const float2*>(row);
                a[wr][0] = hl ? __ldg(row - 1) : 0.0f;
                a[wr][1] = m.x;
                a[wr][2] = m.y;
                a[wr][3] = hr ? __ldg(row + 2) : 0.0f;
            } else {
                a[wr][0] = a[wr][1] = a[wr][2] = a[wr][3] = 0.0f;
            }
        }

        float acc00 = 0.f, acc01 = 0.f, acc10 = 0.f, acc11 = 0.f;
#pragma unroll
        for (int wr = 0; wr < 4; wr++) {
            if (wr < 3) {
#pragma unroll
                for (int dx = 0; dx < 3; dx++) {
                    acc00 = fmaf(s[0][0][wr * 3 + dx], a[wr][dx],     acc00);
                    acc01 = fmaf(s[0][1][wr * 3 + dx], a[wr][dx + 1], acc01);
                }
            }
            if (wr > 0) {
                const int dy = wr - 1;
#pragma unroll
                for (int dx = 0; dx < 3; dx++) {
                    acc10 = fmaf(s[1][0][dy * 3 + dx], a[wr][dx],     acc10);
                    acc11 = fmaf(s[1][1][dy * 3 + dx], a[wr][dx + 1], acc11);
                }
            }
        }

        float2 o0; o0.x = acc00; o0.y = acc01;
        float2 o1; o1.x = acc10; o1.y = acc11;
        *reinterpret_cast<float2*>(ob + (size_t)c * HW_ + h0 * W_ + w0)       = o0;
        *reinterpret_cast<float2*>(ob + (size_t)c * HW_ + (h0 + 1) * W_ + w0) = o1;
    }
}

extern "C" void kernel_launch(void* const* d_in, const int* in_sizes, int n_in,
                              void* d_out, int out_size)
{
    const float* q = (const float*)d_in[0];
    const float* k = (const float*)d_in[1];
    const float* v = (const float*)d_in[2];
    float* out = (float*)d_out;

    dim3 block(128, 2);         // 256 threads: 2 row-pairs x full 256-px width
    dim3 grid(1, H_ / 4, B_);   // 64 x 8 = 512 blocks
    conv_attn_rr<<<grid, block>>>(q, k, v, out);
}

// round 9
// speedup vs baseline: 1.7426x; 1.1591x over previous
#include <cuda_runtime.h>
#include <cstdint>

#define B_ 8
#define C_ 64
#define H_ 256
#define W_ 256
#define HW_ (H_ * W_)
#define TH 4                  // output rows per block
#define ROWS (TH + 2)         // staged input rows (with halo)
#define NS 4                  // pipeline depth (ring buffers)
#define RSTRIDE 264           // idx3 = left zero guard, 4..259 = data, 260 = right zero guard

__device__ __forceinline__ void cp16(uint32_t dst, const float* src) {
    asm volatile("cp.async.cg.shared.global [%0], [%1], 16;" :: "r"(dst), "l"(src));
}
__device__ __forceinline__ void cp_commit() {
    asm volatile("cp.async.commit_group;");
}
__device__ __forceinline__ void cp_wait3() {
    asm volatile("cp.async.wait_group 3;");
}

__global__ __launch_bounds__(512, 3)
void conv_attn_p512(const float* __restrict__ q, const float* __restrict__ k,
                    const float* __restrict__ v, float* __restrict__ out)
{
    __shared__ __align__(16) float ring[NS][ROWS][RSTRIDE];

    const int tid = threadIdx.x;
    const int x   = tid & 127;         // 128 float2 groups per row
    const int y   = tid >> 7;          // output row 0..3
    const int w0  = x * 2;
    const int h0  = blockIdx.x * TH;
    const int b   = blockIdx.y;

    const size_t cb = (size_t)b * C_ * HW_;
    const float* qb = q + cb;
    const float* kb = k + cb;
    const float* vb = v + cb;
    float*       ob = out + cb;
    const int rowoff = (h0 + y) * W_ + w0;

    // zero guard cells once (never overwritten by staging)
    if (tid < NS * ROWS) {
        ring[tid / ROWS][tid % ROWS][3]   = 0.0f;
        ring[tid / ROWS][tid % ROWS][260] = 0.0f;
    }

    const uint32_t ring_s = (uint32_t)__cvta_generic_to_shared(&ring[0][0][0]);

    // stage channel c of tensor `srcb` into ring[c % NS]; 384 float4 slots
    auto stage = [&](const float* srcb, int c) {
        if (tid < ROWS * 64) {
            const int      bi   = c & (NS - 1);
            const uint32_t bufb = ring_s + (uint32_t)bi * (ROWS * RSTRIDE * 4);
            const float*   chan = srcb + (size_t)c * HW_;
            const int r   = tid >> 6;             // 0..5
            const int col = (tid & 63) * 4;       // 0..252
            const int hh  = h0 - 1 + r;
            if (hh >= 0 && hh < H_) {
                cp16(bufb + (uint32_t)(r * RSTRIDE + 4 + col) * 4, chan + hh * W_ + col);
            } else {
                float4 z = make_float4(0.f, 0.f, 0.f, 0.f);
                *reinterpret_cast<float4*>(&ring[bi][r][4 + col]) = z;
            }
        }
    };

    float s[2][9];
#pragma unroll
    for (int j = 0; j < 2; j++)
#pragma unroll
        for (int i = 0; i < 9; i++) s[j][i] = 0.0f;

    // ================= Pass 1: scores =================
    for (int c = 0; c < 3; c++) { stage(kb, c); cp_commit(); }
    float2 qcur = *reinterpret_cast<const float2*>(qb + rowoff);

#pragma unroll 1
    for (int c = 0; c < C_; c++) {
        if (c + 3 < C_) stage(kb, c + 3);
        cp_commit();
        cp_wait3();
        __syncthreads();

        float2 qnext;
        if (c + 1 < C_)
            qnext = *reinterpret_cast<const float2*>(qb + (size_t)(c + 1) * HW_ + rowoff);

        const int bi = c & (NS - 1);
#pragma unroll
        for (int dy = 0; dy < 3; dy++) {
            const float* rp = &ring[bi][y + dy][4 + w0];
            const float2 m = *reinterpret_cast<const float2*>(rp);
            const float  l = rp[-1];
            const float  r = rp[2];
            s[0][dy*3+0] = fmaf(qcur.x, l,   s[0][dy*3+0]);
            s[0][dy*3+1] = fmaf(qcur.x, m.x, s[0][dy*3+1]);
            s[0][dy*3+2] = fmaf(qcur.x, m.y, s[0][dy*3+2]);
            s[1][dy*3+0] = fmaf(qcur.y, m.x, s[1][dy*3+0]);
            s[1][dy*3+1] = fmaf(qcur.y, m.y, s[1][dy*3+1]);
            s[1][dy*3+2] = fmaf(qcur.y, r,   s[1][dy*3+2]);
        }
        qcur = qnext;
        __syncthreads();
    }

    // ================= Softmax over 9 taps (OOB taps = score 0, zero-pad semantics) =================
#pragma unroll
    for (int j = 0; j < 2; j++) {
        float mx = s[j][0];
#pragma unroll
        for (int i = 1; i < 9; i++) mx = fmaxf(mx, s[j][i]);
        float sum = 0.0f;
#pragma unroll
        for (int i = 0; i < 9; i++) { s[j][i] = __expf(s[j][i] - mx); sum += s[j][i]; }
        const float inv = 1.0f / sum;
#pragma unroll
        for (int i = 0; i < 9; i++) s[j][i] *= inv;
    }

    // ================= Pass 2: weighted v sum =================
    for (int c = 0; c < 3; c++) { stage(vb, c); cp_commit(); }

#pragma unroll 1
    for (int c = 0; c < C_; c++) {
        if (c + 3 < C_) stage(vb, c + 3);
        cp_commit();
        cp_wait3();
        __syncthreads();

        float acc0 = 0.f, acc1 = 0.f;
        const int bi = c & (NS - 1);
#pragma unroll
        for (int dy = 0; dy < 3; dy++) {
            const float* rp = &ring[bi][y + dy][4 + w0];
            const float2 m = *reinterpret_cast<const float2*>(rp);
            const float  l = rp[-1];
            const float  r = rp[2];
            acc0 = fmaf(s[0][dy*3+0], l,   acc0);
            acc0 = fmaf(s[0][dy*3+1], m.x, acc0);
            acc0 = fmaf(s[0][dy*3+2], m.y, acc0);
            acc1 = fmaf(s[1][dy*3+0], m.x, acc1);
            acc1 = fmaf(s[1][dy*3+1], m.y, acc1);
            acc1 = fmaf(s[1][dy*3+2], r,   acc1);
        }

        float2 o; o.x = acc0; o.y = acc1;
        *reinterpret_cast<float2*>(ob + (size_t)c * HW_ + rowoff) = o;
        __syncthreads();
    }
}

extern "C" void kernel_launch(void* const* d_in, const int* in_sizes, int n_in,
                              void* d_out, int out_size)
{
    const float* q = (const float*)d_in[0];
    const float* k = (const float*)d_in[1];
    const float* v = (const float*)d_in[2];
    float* out = (float*)d_out;

    dim3 block(512);            // 4 rows x 128 float2-groups
    dim3 grid(H_ / TH, B_);     // 64 x 8 = 512 blocks
    conv_attn_p512<<<grid, block>>>(q, k, v, out);
}

// round 10
// speedup vs baseline: 2.5346x; 1.4545x over previous
#include <cuda_runtime.h>
#include <cstdint>

#define B_ 8
#define C_ 64
#define H_ 256
#define W_ 256
#define HW_ (H_ * W_)
#define TH 4                  // output rows per block
#define ROWS (TH + 2)         // staged input rows (with halo)
#define NS 4                  // pipeline depth (ring buffers)
#define RSTRIDE 264           // idx3 = left zero guard, 4..259 = data, 260 = right zero guard
#define FULLMASK 0xffffffffu

__device__ __forceinline__ void cp16(uint32_t dst, const float* src) {
    asm volatile("cp.async.cg.shared.global [%0], [%1], 16;" :: "r"(dst), "l"(src));
}
__device__ __forceinline__ void cp_commit() {
    asm volatile("cp.async.commit_group;");
}
__device__ __forceinline__ void cp_wait2() {
    asm volatile("cp.async.wait_group 2;");
}

__global__ __launch_bounds__(256, 4)
void conv_attn_v10(const float* __restrict__ q, const float* __restrict__ k,
                   const float* __restrict__ v, float* __restrict__ out)
{
    __shared__ __align__(16) float ring[NS][ROWS][RSTRIDE];

    const int tid  = threadIdx.x;
    const int lane = tid & 31;
    const int x    = tid & 63;         // 64 groups of 4 px; warp = 128 contiguous px of one row
    const int y    = tid >> 6;         // output row 0..3
    const int w0   = x * 4;
    const int h0   = blockIdx.x * TH;
    const int b    = blockIdx.y;

    const size_t cb = (size_t)b * C_ * HW_;
    const float* qb = q + cb;
    const float* kb = k + cb;
    const float* vb = v + cb;
    float*       ob = out + cb;
    const int rowoff = (h0 + y) * W_ + w0;

    // zero guard cells once (never overwritten by staging)
    for (int i = tid; i < NS * ROWS; i += 256) {
        ring[i / ROWS][i % ROWS][3]   = 0.0f;
        ring[i / ROWS][i % ROWS][260] = 0.0f;
    }

    const uint32_t ring_s = (uint32_t)__cvta_generic_to_shared(&ring[0][0][0]);

    // stage channel c of tensor `srcb` into ring[c & 3]
    auto stage = [&](const float* srcb, int c) {
        const int      bi   = c & (NS - 1);
        const uint32_t bufb = ring_s + (uint32_t)bi * (ROWS * RSTRIDE * 4);
        const float*   chan = srcb + (size_t)c * HW_;
        #pragma unroll
        for (int slot = tid; slot < ROWS * 64; slot += 256) {
            const int r   = slot >> 6;
            const int col = (slot & 63) * 4;
            const int hh  = h0 - 1 + r;
            if (hh >= 0 && hh < H_) {
                cp16(bufb + (uint32_t)(r * RSTRIDE + 4 + col) * 4, chan + hh * W_ + col);
            } else {
                float4 z = make_float4(0.f, 0.f, 0.f, 0.f);
                *reinterpret_cast<float4*>(&ring[bi][r][4 + col]) = z;
            }
        }
    };

    float s[4][9];
#pragma unroll
    for (int j = 0; j < 4; j++)
#pragma unroll
        for (int i = 0; i < 9; i++) s[j][i] = 0.0f;

    // ================= Pass 1: scores =================
    stage(kb, 0); cp_commit();
    stage(kb, 1); cp_commit();
    stage(kb, 2); cp_commit();
    float4 qcur = *reinterpret_cast<const float4*>(qb + rowoff);

#pragma unroll 1
    for (int c = 0; c < C_; c++) {
        cp_wait2();              // channel c's group complete (3 groups pending -> 2)
        __syncthreads();         // single barrier: also separates last iter's reads from this iter's stage

        float4 qnext;
        if (c + 1 < C_)
            qnext = *reinterpret_cast<const float4*>(qb + (size_t)(c + 1) * HW_ + rowoff);

        const float qa[4] = {qcur.x, qcur.y, qcur.z, qcur.w};
        const int bi = c & (NS - 1);
#pragma unroll
        for (int dy = 0; dy < 3; dy++) {
            const float* rp = &ring[bi][y + dy][4 + w0];
            const float4 m = *reinterpret_cast<const float4*>(rp);
            float lft = __shfl_up_sync(FULLMASK, m.w, 1);
            float rgt = __shfl_down_sync(FULLMASK, m.x, 1);
            if (lane == 0)  lft = rp[-1];   // guard cell gives 0 at w=0
            if (lane == 31) rgt = rp[4];    // guard cell gives 0 at w=255

            const float a[6] = {lft, m.x, m.y, m.z, m.w, rgt};
#pragma unroll
            for (int j = 0; j < 4; j++)
#pragma unroll
                for (int dx = 0; dx < 3; dx++)
                    s[j][dy * 3 + dx] = fmaf(qa[j], a[j + dx], s[j][dy * 3 + dx]);
        }

        // stage channel c+3 (overwrites buffer read at iter c-1; safe past this iter's sync)
        if (c + 3 < C_) stage(kb, c + 3);
        cp_commit();             // empty group on tail iters keeps wait accounting uniform
        qcur = qnext;
    }
    __syncthreads();             // protect ring before pass-2 prologue overwrites it

    // ================= Softmax over 9 taps (OOB taps = score 0, zero-pad semantics) =================
#pragma unroll
    for (int j = 0; j < 4; j++) {
        float mx = s[j][0];
#pragma unroll
        for (int i = 1; i < 9; i++) mx = fmaxf(mx, s[j][i]);
        float sum = 0.0f;
#pragma unroll
        for (int i = 0; i < 9; i++) { s[j][i] = __expf(s[j][i] - mx); sum += s[j][i]; }
        const float inv = 1.0f / sum;
#pragma unroll
        for (int i = 0; i < 9; i++) s[j][i] *= inv;
    }

    // ================= Pass 2: weighted v sum =================
    stage(vb, 0); cp_commit();
    stage(vb, 1); cp_commit();
    stage(vb, 2); cp_commit();

#pragma unroll 1
    for (int c = 0; c < C_; c++) {
        cp_wait2();
        __syncthreads();

        float acc[4] = {0.f, 0.f, 0.f, 0.f};
        const int bi = c & (NS - 1);
#pragma unroll
        for (int dy = 0; dy < 3; dy++) {
            const float* rp = &ring[bi][y + dy][4 + w0];
            const float4 m = *reinterpret_cast<const float4*>(rp);
            float lft = __shfl_up_sync(FULLMASK, m.w, 1);
            float rgt = __shfl_down_sync(FULLMASK, m.x, 1);
            if (lane == 0)  lft = rp[-1];
            if (lane == 31) rgt = rp[4];

            const float a[6] = {lft, m.x, m.y, m.z, m.w, rgt};
#pragma unroll
            for (int j = 0; j < 4; j++)
#pragma unroll
                for (int dx = 0; dx < 3; dx++)
                    acc[j] = fmaf(s[j][dy * 3 + dx], a[j + dx], acc[j]);
        }

        if (c + 3 < C_) stage(vb, c + 3);
        cp_commit();

        float4 o;
        o.x = acc[0]; o.y = acc[1]; o.z = acc[2]; o.w = acc[3];
        *reinterpret_cast<float4*>(ob + (size_t)c * HW_ + rowoff) = o;
    }
}

extern "C" void kernel_launch(void* const* d_in, const int* in_sizes, int n_in,
                              void* d_out, int out_size)
{
    const float* q = (const float*)d_in[0];
    const float* k = (const float*)d_in[1];
    const float* v = (const float*)d_in[2];
    float* out = (float*)d_out;

    dim3 block(256);
    dim3 grid(H_ / TH, B_);     // 64 x 8 = 512 blocks
    conv_attn_v10<<<grid, block>>>(q, k, v, out);
}